// round 1
// baseline (speedup 1.0000x reference)
#include <cuda_runtime.h>

#define NTOK 8192
#define DIM 4096
#define ODIM 4096
#define NEXP 8
#define RNK 16
#define KLORA 128
#define SCALING_F 2.0f
#define MAXTHR 0.125f

// scratch (no dynamic allocation allowed)
__device__ float g_w[NTOK * NEXP];    // scaled, normalized expert weights
__device__ float g_g[NTOK * KLORA];   // g[n, e*16+r] = w[n,e] * h[n,e,r]

// ---------------------------------------------------------------------------
// Kernel 1: gating. 4 tokens per block, 256 threads.
// Computes softmax(x@Wg^T), thr = sigmoid(x@Wt + b)*0.125, masked+normalized
// weights, scaled by SCALING. Weight matrices (144KB) stay L2-resident.
// ---------------------------------------------------------------------------
#define GT 4
__global__ void gate_kernel(const float* __restrict__ x,
                            const float* __restrict__ Wg,
                            const float* __restrict__ Wt,
                            const float* __restrict__ bt) {
    int n0 = blockIdx.x * GT;
    int tid = threadIdx.x;

    float acc[GT][9];
#pragma unroll
    for (int t = 0; t < GT; t++)
#pragma unroll
        for (int i = 0; i < 9; i++) acc[t][i] = 0.f;

    for (int d = tid; d < DIM; d += 256) {
        float wv[9];
#pragma unroll
        for (int e = 0; e < NEXP; e++) wv[e] = Wg[e * DIM + d];
        wv[8] = Wt[d];
#pragma unroll
        for (int t = 0; t < GT; t++) {
            float xv = x[(size_t)(n0 + t) * DIM + d];
#pragma unroll
            for (int i = 0; i < 9; i++) acc[t][i] = fmaf(xv, wv[i], acc[t][i]);
        }
    }

    // warp reduce
#pragma unroll
    for (int t = 0; t < GT; t++)
#pragma unroll
        for (int i = 0; i < 9; i++)
#pragma unroll
            for (int off = 16; off; off >>= 1)
                acc[t][i] += __shfl_down_sync(0xffffffffu, acc[t][i], off);

    __shared__ float sred[8][GT][9];
    int warp = tid >> 5, lane = tid & 31;
    if (lane == 0) {
#pragma unroll
        for (int t = 0; t < GT; t++)
#pragma unroll
            for (int i = 0; i < 9; i++) sred[warp][t][i] = acc[t][i];
    }
    __syncthreads();

    if (tid < GT) {
        int t = tid;
        float v[9];
#pragma unroll
        for (int i = 0; i < 9; i++) {
            float s = 0.f;
#pragma unroll
            for (int w2 = 0; w2 < 8; w2++) s += sred[w2][t][i];
            v[i] = s;
        }
        float mx = v[0];
#pragma unroll
        for (int e = 1; e < NEXP; e++) mx = fmaxf(mx, v[e]);
        float se = 0.f, gate[NEXP];
#pragma unroll
        for (int e = 0; e < NEXP; e++) { gate[e] = expf(v[e] - mx); se += gate[e]; }
        float inv = 1.f / se;
        float thr = MAXTHR / (1.f + expf(-(v[8] + bt[0])));
        float w[NEXP]; float ws = 0.f;
#pragma unroll
        for (int e = 0; e < NEXP; e++) {
            float a = gate[e] * inv - thr;
            w[e] = (a >= 0.f) ? a : 0.f;
            ws += w[e];
        }
        if (ws == 0.f) ws = 1.f;
        float sc = SCALING_F / ws;
#pragma unroll
        for (int e = 0; e < NEXP; e++) g_w[(n0 + t) * NEXP + e] = w[e] * sc;
    }
}

// ---------------------------------------------------------------------------
// Kernel 2: h = x @ A_flat^T  ([N,4096]@[4096,128]), epilogue: g = h * w.
// BM=64, BN=128, BK=16, 256 threads, 4x8 outputs/thread.
// ---------------------------------------------------------------------------
__global__ __launch_bounds__(256)
void h_gemm_kernel(const float* __restrict__ x,
                   const float* __restrict__ Aw) {
    __shared__ float As[16][68];    // [k][m], padded
    __shared__ float Bs[16][132];   // [k][kcol], padded

    int tid = threadIdx.x;
    int tx = tid & 15;       // 0..15, cols
    int ty = tid >> 4;       // 0..15, rows (4 rows each)
    int m0 = blockIdx.x * 64;

    int lr = tid >> 2;         // 0..63
    int lc = (tid & 3) * 4;    // 0,4,8,12

    float acc[4][8];
#pragma unroll
    for (int i = 0; i < 4; i++)
#pragma unroll
        for (int j = 0; j < 8; j++) acc[i][j] = 0.f;

    for (int t = 0; t < DIM / 16; ++t) {
        int k0 = t * 16;
        float4 a0 = *(const float4*)&x[(size_t)(m0 + lr) * DIM + k0 + lc];
        float4 b0 = *(const float4*)&Aw[(size_t)lr * DIM + k0 + lc];
        float4 b1 = *(const float4*)&Aw[(size_t)(lr + 64) * DIM + k0 + lc];
        __syncthreads();
        As[lc + 0][lr] = a0.x; As[lc + 1][lr] = a0.y;
        As[lc + 2][lr] = a0.z; As[lc + 3][lr] = a0.w;
        Bs[lc + 0][lr] = b0.x; Bs[lc + 1][lr] = b0.y;
        Bs[lc + 2][lr] = b0.z; Bs[lc + 3][lr] = b0.w;
        Bs[lc + 0][lr + 64] = b1.x; Bs[lc + 1][lr + 64] = b1.y;
        Bs[lc + 2][lr + 64] = b1.z; Bs[lc + 3][lr + 64] = b1.w;
        __syncthreads();
#pragma unroll
        for (int kk = 0; kk < 16; kk++) {
            float a[4], b[8];
            *(float4*)&a[0] = *(float4*)&As[kk][ty * 4];
            *(float4*)&b[0] = *(float4*)&Bs[kk][tx * 8];
            *(float4*)&b[4] = *(float4*)&Bs[kk][tx * 8 + 4];
#pragma unroll
            for (int i = 0; i < 4; i++)
#pragma unroll
                for (int j = 0; j < 8; j++) acc[i][j] = fmaf(a[i], b[j], acc[i][j]);
        }
    }

#pragma unroll
    for (int i = 0; i < 4; i++) {
        int n = m0 + ty * 4 + i;
#pragma unroll
        for (int j = 0; j < 8; j++) {
            int k = tx * 8 + j;
            g_g[(size_t)n * KLORA + k] = acc[i][j] * g_w[n * NEXP + (k >> 4)];
        }
    }
}

// ---------------------------------------------------------------------------
// Kernel 3: main GEMM. out = x @ W_base^T + g @ B2 + b_base.
// BM=BN=128, BK=16, 256 threads, 8x8 outputs/thread.
// K loop = 256 tiles over (x, W_base) then 8 tiles over (g, B_w).
// ---------------------------------------------------------------------------
__global__ __launch_bounds__(256, 2)
void main_gemm_kernel(const float* __restrict__ x,
                      const float* __restrict__ Wb,
                      const float* __restrict__ bb,
                      const float* __restrict__ Bw,
                      float* __restrict__ out) {
    __shared__ float As[16][132];
    __shared__ float Bs[16][132];

    int tid = threadIdx.x;
    int tx = tid & 15;
    int ty = tid >> 4;
    int m0 = blockIdx.y * 128;
    int n0 = blockIdx.x * 128;

    int lr = tid >> 2;          // 0..63
    int lc = (tid & 3) * 4;     // 0,4,8,12

    float acc[8][8];
#pragma unroll
    for (int i = 0; i < 8; i++)
#pragma unroll
        for (int j = 0; j < 8; j++) acc[i][j] = 0.f;

    // ---- main K loop over W_base (K = 4096) ----
    for (int t = 0; t < DIM / 16; ++t) {
        int k0 = t * 16;
        float4 a0 = *(const float4*)&x [(size_t)(m0 + lr)      * DIM + k0 + lc];
        float4 a1 = *(const float4*)&x [(size_t)(m0 + lr + 64) * DIM + k0 + lc];
        float4 b0 = *(const float4*)&Wb[(size_t)(n0 + lr)      * DIM + k0 + lc];
        float4 b1 = *(const float4*)&Wb[(size_t)(n0 + lr + 64) * DIM + k0 + lc];
        __syncthreads();
        As[lc + 0][lr] = a0.x; As[lc + 1][lr] = a0.y;
        As[lc + 2][lr] = a0.z; As[lc + 3][lr] = a0.w;
        As[lc + 0][lr + 64] = a1.x; As[lc + 1][lr + 64] = a1.y;
        As[lc + 2][lr + 64] = a1.z; As[lc + 3][lr + 64] = a1.w;
        Bs[lc + 0][lr] = b0.x; Bs[lc + 1][lr] = b0.y;
        Bs[lc + 2][lr] = b0.z; Bs[lc + 3][lr] = b0.w;
        Bs[lc + 0][lr + 64] = b1.x; Bs[lc + 1][lr + 64] = b1.y;
        Bs[lc + 2][lr + 64] = b1.z; Bs[lc + 3][lr + 64] = b1.w;
        __syncthreads();
#pragma unroll
        for (int kk = 0; kk < 16; kk++) {
            float a[8], b[8];
            *(float4*)&a[0] = *(float4*)&As[kk][ty * 8];
            *(float4*)&a[4] = *(float4*)&As[kk][ty * 8 + 4];
            *(float4*)&b[0] = *(float4*)&Bs[kk][tx * 8];
            *(float4*)&b[4] = *(float4*)&Bs[kk][tx * 8 + 4];
#pragma unroll
            for (int i = 0; i < 8; i++)
#pragma unroll
                for (int j = 0; j < 8; j++) acc[i][j] = fmaf(a[i], b[j], acc[i][j]);
        }
    }

    // ---- LoRA K loop: 8 tiles of 16 over (g, B_w[e]) ----
    for (int e = 0; e < NEXP; ++e) {
        int k0 = e * 16;
        float4 a0 = *(const float4*)&g_g[(size_t)(m0 + lr)      * KLORA + k0 + lc];
        float4 a1 = *(const float4*)&g_g[(size_t)(m0 + lr + 64) * KLORA + k0 + lc];
        // B_w[e][o][r]: row o = n0+lr(+64), r = lc..lc+3 (contiguous)
        float4 b0 = *(const float4*)&Bw[((size_t)e * ODIM + n0 + lr)      * RNK + lc];
        float4 b1 = *(const float4*)&Bw[((size_t)e * ODIM + n0 + lr + 64) * RNK + lc];
        __syncthreads();
        As[lc + 0][lr] = a0.x; As[lc + 1][lr] = a0.y;
        As[lc + 2][lr] = a0.z; As[lc + 3][lr] = a0.w;
        As[lc + 0][lr + 64] = a1.x; As[lc + 1][lr + 64] = a1.y;
        As[lc + 2][lr + 64] = a1.z; As[lc + 3][lr + 64] = a1.w;
        Bs[lc + 0][lr] = b0.x; Bs[lc + 1][lr] = b0.y;
        Bs[lc + 2][lr] = b0.z; Bs[lc + 3][lr] = b0.w;
        Bs[lc + 0][lr + 64] = b1.x; Bs[lc + 1][lr + 64] = b1.y;
        Bs[lc + 2][lr + 64] = b1.z; Bs[lc + 3][lr + 64] = b1.w;
        __syncthreads();
#pragma unroll
        for (int kk = 0; kk < 16; kk++) {
            float a[8], b[8];
            *(float4*)&a[0] = *(float4*)&As[kk][ty * 8];
            *(float4*)&a[4] = *(float4*)&As[kk][ty * 8 + 4];
            *(float4*)&b[0] = *(float4*)&Bs[kk][tx * 8];
            *(float4*)&b[4] = *(float4*)&Bs[kk][tx * 8 + 4];
#pragma unroll
            for (int i = 0; i < 8; i++)
#pragma unroll
                for (int j = 0; j < 8; j++) acc[i][j] = fmaf(a[i], b[j], acc[i][j]);
        }
    }

    // ---- epilogue: + bias, store ----
#pragma unroll
    for (int i = 0; i < 8; i++) {
        int m = m0 + ty * 8 + i;
#pragma unroll
        for (int jj = 0; jj < 2; jj++) {
            int o = n0 + tx * 8 + jj * 4;
            float4 bias = *(const float4*)&bb[o];
            float4 v;
            v.x = acc[i][jj * 4 + 0] + bias.x;
            v.y = acc[i][jj * 4 + 1] + bias.y;
            v.z = acc[i][jj * 4 + 2] + bias.z;
            v.w = acc[i][jj * 4 + 3] + bias.w;
            *(float4*)&out[(size_t)m * ODIM + o] = v;
        }
    }
}

// ---------------------------------------------------------------------------
extern "C" void kernel_launch(void* const* d_in, const int* in_sizes, int n_in,
                              void* d_out, int out_size) {
    const float* x   = (const float*)d_in[0];   // [B,S,D]
    const float* Wb  = (const float*)d_in[1];   // [O,D]
    const float* bb  = (const float*)d_in[2];   // [O]
    const float* Wg  = (const float*)d_in[3];   // [E,D]
    const float* Wt  = (const float*)d_in[4];   // [D]
    const float* bt  = (const float*)d_in[5];   // [1]
    const float* Aw  = (const float*)d_in[6];   // [E,R,D]
    const float* Bw  = (const float*)d_in[7];   // [E,O,R]
    float* out = (float*)d_out;

    gate_kernel<<<NTOK / GT, 256>>>(x, Wg, Wt, bt);
    h_gemm_kernel<<<NTOK / 64, 256>>>(x, Aw);
    dim3 grid(ODIM / 128, NTOK / 128);
    main_gemm_kernel<<<grid, 256>>>(x, Wb, bb, Bw, out);
}

// round 3
// speedup vs baseline: 2.2295x; 2.2295x over previous
#include <cuda_runtime.h>
#include <cuda_bf16.h>
#include <cstdint>

#define NTOK 8192
#define DIM 4096
#define ODIM 4096
#define NEXP 8
#define RNK 16
#define KLORA 128
#define SCALING_F 2.0f
#define MAXTHR 0.125f

// ---------------- device scratch (no dynamic allocation allowed) ------------
__device__ float g_w[NTOK * NEXP];
__device__ __nv_bfloat16 g_xhi[(size_t)NTOK * DIM];
__device__ __nv_bfloat16 g_xlo[(size_t)NTOK * DIM];
__device__ __nv_bfloat16 g_Whi[(size_t)ODIM * DIM];
__device__ __nv_bfloat16 g_Wlo[(size_t)ODIM * DIM];
__device__ __nv_bfloat16 g_Ahi[KLORA * DIM];
__device__ __nv_bfloat16 g_Alo[KLORA * DIM];
__device__ __nv_bfloat16 g_Bchi[ODIM * KLORA];
__device__ __nv_bfloat16 g_Bclo[ODIM * KLORA];
__device__ __nv_bfloat16 g_ghi[NTOK * KLORA];
__device__ __nv_bfloat16 g_glo[NTOK * KLORA];

// ---------------- PTX helpers -----------------------------------------------
__device__ __forceinline__ uint32_t smem_u32(const void* p) {
    uint32_t a;
    asm("{ .reg .u64 t; cvta.to.shared.u64 t, %1; cvt.u32.u64 %0, t; }" : "=r"(a) : "l"(p));
    return a;
}
__device__ __forceinline__ void cp16(uint32_t dst, const void* src) {
    asm volatile("cp.async.cg.shared.global [%0], [%1], 16;" :: "r"(dst), "l"(src));
}
#define CP_COMMIT() asm volatile("cp.async.commit_group;" ::: "memory")
#define CP_WAIT1()  asm volatile("cp.async.wait_group 1;" ::: "memory")

__device__ __forceinline__ void ldsm4(uint32_t& r0, uint32_t& r1, uint32_t& r2, uint32_t& r3,
                                      uint32_t addr) {
    asm volatile("ldmatrix.sync.aligned.m8n8.x4.shared.b16 {%0,%1,%2,%3}, [%4];"
                 : "=r"(r0), "=r"(r1), "=r"(r2), "=r"(r3) : "r"(addr));
}
__device__ __forceinline__ void mma16816(float* d, const uint32_t* a, const uint32_t* b) {
    asm volatile("mma.sync.aligned.m16n8k16.row.col.f32.bf16.bf16.f32 "
                 "{%0,%1,%2,%3}, {%4,%5,%6,%7}, {%8,%9}, {%0,%1,%2,%3};"
                 : "+f"(d[0]), "+f"(d[1]), "+f"(d[2]), "+f"(d[3])
                 : "r"(a[0]), "r"(a[1]), "r"(a[2]), "r"(a[3]), "r"(b[0]), "r"(b[1]));
}

// ---------------- split helpers ---------------------------------------------
__device__ __forceinline__ void split1(float v, __nv_bfloat16& h, __nv_bfloat16& l) {
    h = __float2bfloat16(v);
    l = __float2bfloat16(v - __bfloat162float(h));
}
__global__ void split_kernel(const float* __restrict__ src, int which, int n4) {
    __nv_bfloat16 *hi, *lo;
    if (which == 0)      { hi = g_xhi; lo = g_xlo; }
    else if (which == 1) { hi = g_Whi; lo = g_Wlo; }
    else                 { hi = g_Ahi; lo = g_Alo; }
    int i = blockIdx.x * blockDim.x + threadIdx.x;
    if (i >= n4) return;
    float4 v = ((const float4*)src)[i];
    __nv_bfloat16 h0, h1, h2, h3, l0, l1, l2, l3;
    split1(v.x, h0, l0); split1(v.y, h1, l1); split1(v.z, h2, l2); split1(v.w, h3, l3);
    ((__nv_bfloat162*)hi)[2 * i]     = __nv_bfloat162(h0, h1);
    ((__nv_bfloat162*)hi)[2 * i + 1] = __nv_bfloat162(h2, h3);
    ((__nv_bfloat162*)lo)[2 * i]     = __nv_bfloat162(l0, l1);
    ((__nv_bfloat162*)lo)[2 * i + 1] = __nv_bfloat162(l2, l3);
}
__global__ void build_bc_kernel(const float* __restrict__ Bw) {
    int idx = blockIdx.x * blockDim.x + threadIdx.x;   // o*128 + k
    if (idx >= ODIM * KLORA) return;
    int o = idx >> 7, k = idx & 127;
    int e = k >> 4, r = k & 15;
    float v = Bw[((size_t)e * ODIM + o) * RNK + r];
    __nv_bfloat16 h, l; split1(v, h, l);
    g_Bchi[idx] = h; g_Bclo[idx] = l;
}

// ---------------- gate kernel -----------------------------------------------
#define GT 4
__global__ void gate_kernel(const float* __restrict__ x,
                            const float* __restrict__ Wg,
                            const float* __restrict__ Wt,
                            const float* __restrict__ bt) {
    int n0 = blockIdx.x * GT;
    int tid = threadIdx.x;
    float acc[GT][9];
#pragma unroll
    for (int t = 0; t < GT; t++)
#pragma unroll
        for (int i = 0; i < 9; i++) acc[t][i] = 0.f;
    for (int d = tid; d < DIM; d += 256) {
        float wv[9];
#pragma unroll
        for (int e = 0; e < NEXP; e++) wv[e] = Wg[e * DIM + d];
        wv[8] = Wt[d];
#pragma unroll
        for (int t = 0; t < GT; t++) {
            float xv = x[(size_t)(n0 + t) * DIM + d];
#pragma unroll
            for (int i = 0; i < 9; i++) acc[t][i] = fmaf(xv, wv[i], acc[t][i]);
        }
    }
#pragma unroll
    for (int t = 0; t < GT; t++)
#pragma unroll
        for (int i = 0; i < 9; i++)
#pragma unroll
            for (int off = 16; off; off >>= 1)
                acc[t][i] += __shfl_down_sync(0xffffffffu, acc[t][i], off);
    __shared__ float sred[8][GT][9];
    int warp = tid >> 5, lane = tid & 31;
    if (lane == 0)
#pragma unroll
        for (int t = 0; t < GT; t++)
#pragma unroll
            for (int i = 0; i < 9; i++) sred[warp][t][i] = acc[t][i];
    __syncthreads();
    if (tid < GT) {
        int t = tid;
        float v[9];
#pragma unroll
        for (int i = 0; i < 9; i++) {
            float s = 0.f;
#pragma unroll
            for (int w2 = 0; w2 < 8; w2++) s += sred[w2][t][i];
            v[i] = s;
        }
        float mx = v[0];
#pragma unroll
        for (int e = 1; e < NEXP; e++) mx = fmaxf(mx, v[e]);
        float se = 0.f, gate[NEXP];
#pragma unroll
        for (int e = 0; e < NEXP; e++) { gate[e] = expf(v[e] - mx); se += gate[e]; }
        float inv = 1.f / se;
        float thr = MAXTHR / (1.f + expf(-(v[8] + bt[0])));
        float w[NEXP]; float ws = 0.f;
#pragma unroll
        for (int e = 0; e < NEXP; e++) {
            float a = gate[e] * inv - thr;
            w[e] = (a >= 0.f) ? a : 0.f;
            ws += w[e];
        }
        if (ws == 0.f) ws = 1.f;
        float sc = SCALING_F / ws;
#pragma unroll
        for (int e = 0; e < NEXP; e++) g_w[(n0 + t) * NEXP + e] = w[e] * sc;
    }
}

// ---------------- HMMA GEMM --------------------------------------------------
// smem tile: 128 rows x 32 bf16 cols, row stride 80B (conflict-free ldmatrix)
#define RS 80
#define TILE_B (128 * RS)          // 10240 B
#define STAGE_B (4 * TILE_B)       // 40960 B  (Ahi, Alo, Bhi, Blo)
#define NSTG 3

template <int MODE>
__device__ __forceinline__ void issue_chunk(uint32_t sbase, int stage, int chunk,
                                            int m0, int n0, int tid) {
    const __nv_bfloat16 *srcAh, *srcAl, *srcBh, *srcBl;
    int strideA, strideB; int rowOffA, rowOffB; int kcol;
    if (MODE == 1 && chunk >= 128) {
        kcol = (chunk - 128) * 32;
        srcAh = g_ghi;  srcAl = g_glo;  strideA = KLORA; rowOffA = m0;
        srcBh = g_Bchi; srcBl = g_Bclo; strideB = KLORA; rowOffB = n0;
    } else if (MODE == 1) {
        kcol = chunk * 32;
        srcAh = g_xhi; srcAl = g_xlo; strideA = DIM; rowOffA = m0;
        srcBh = g_Whi; srcBl = g_Wlo; strideB = DIM; rowOffB = n0;
    } else {
        kcol = chunk * 32;
        srcAh = g_xhi; srcAl = g_xlo; strideA = DIM; rowOffA = m0;
        srcBh = g_Ahi; srcBl = g_Alo; strideB = DIM; rowOffB = 0;
    }
    uint32_t dstBase = sbase + stage * STAGE_B;
#pragma unroll
    for (int part = 0; part < 2; part++) {
        int c = tid + part * 256;
        int row = c >> 2, k16 = c & 3;
        uint32_t dof = row * RS + k16 * 16;
        size_t offA = (size_t)(rowOffA + row) * strideA + kcol + k16 * 8;
        size_t offB = (size_t)(rowOffB + row) * strideB + kcol + k16 * 8;
        cp16(dstBase + 0 * TILE_B + dof, srcAh + offA);
        cp16(dstBase + 1 * TILE_B + dof, srcAl + offA);
        cp16(dstBase + 2 * TILE_B + dof, srcBh + offB);
        cp16(dstBase + 3 * TILE_B + dof, srcBl + offB);
    }
}

__device__ __forceinline__ void compute_stage(uint32_t sbase, int stage, int wm, int wn,
                                              uint32_t aLane, uint32_t bLane,
                                              float acc[4][4][4]) {
    uint32_t base = sbase + stage * STAGE_B;
    uint32_t aHiB = base + wm * 64 * RS + aLane;
    uint32_t aLoB = aHiB + TILE_B;
    uint32_t bHiB = base + 2 * TILE_B + wn * RS + bLane;
    uint32_t bLoB = bHiB + TILE_B;
#pragma unroll
    for (int s = 0; s < 2; s++) {
        uint32_t ah[4][4], al[4][4];
#pragma unroll
        for (int mt = 0; mt < 4; mt++) {
            ldsm4(ah[mt][0], ah[mt][1], ah[mt][2], ah[mt][3], aHiB + mt * 16 * RS + s * 32);
            ldsm4(al[mt][0], al[mt][1], al[mt][2], al[mt][3], aLoB + mt * 16 * RS + s * 32);
        }
        uint32_t bh[4][2], bl[4][2];
#pragma unroll
        for (int p = 0; p < 2; p++) {
            ldsm4(bh[2 * p][0], bh[2 * p][1], bh[2 * p + 1][0], bh[2 * p + 1][1],
                  bHiB + p * 16 * RS + s * 32);
            ldsm4(bl[2 * p][0], bl[2 * p][1], bl[2 * p + 1][0], bl[2 * p + 1][1],
                  bLoB + p * 16 * RS + s * 32);
        }
#pragma unroll
        for (int mt = 0; mt < 4; mt++)
#pragma unroll
            for (int nt = 0; nt < 4; nt++) {
                mma16816(acc[mt][nt], ah[mt], bh[nt]);
                mma16816(acc[mt][nt], ah[mt], bl[nt]);
                mma16816(acc[mt][nt], al[mt], bh[nt]);
            }
    }
}

// MODE 0: h-gemm (B = A_w splits, BN=128 covers all LoRA rows), 128 chunks,
//         epilogue: g = h*w -> split to ghi/glo.
// MODE 1: main (x/W for 128 chunks + g/Bc for 4 chunks), epilogue: +bias -> out.
template <int MODE>
__global__ __launch_bounds__(256, 1)
void hmma_gemm_kernel(const float* __restrict__ bb, float* __restrict__ out) {
    constexpr int NCHUNK = (MODE == 1) ? 132 : 128;
    extern __shared__ char smem[];
    uint32_t sbase = smem_u32(smem);

    int tid = threadIdx.x;
    int wid = tid >> 5, lane = tid & 31;
    int wm = wid >> 2;             // 0..1  (64-row slab)
    int wn = (wid & 3) * 32;       // 0,32,64,96

    int m0, n0;
    if (MODE == 1) {
        int bid = blockIdx.x;
        int idx = bid & 255;
        int mg = (bid >> 8) & 3;
        int ng = bid >> 10;
        m0 = (mg * 16 + (idx & 15)) * 128;
        n0 = (ng * 16 + (idx >> 4)) * 128;
    } else {
        m0 = blockIdx.x * 128; n0 = 0;
    }

    uint32_t aLane = (uint32_t)((lane & 15) * RS + (lane >> 4) * 16);
    uint32_t bLane = (uint32_t)(((lane & 7) + ((lane >> 4) & 1) * 8) * RS + ((lane >> 3) & 1) * 16);

    float acc[4][4][4];
#pragma unroll
    for (int a = 0; a < 4; a++)
#pragma unroll
        for (int b = 0; b < 4; b++)
#pragma unroll
            for (int c = 0; c < 4; c++) acc[a][b][c] = 0.f;

    // prologue: stages 0,1
    issue_chunk<MODE>(sbase, 0, 0, m0, n0, tid); CP_COMMIT();
    issue_chunk<MODE>(sbase, 1, 1, m0, n0, tid); CP_COMMIT();

#pragma unroll 1
    for (int i = 0; i < NCHUNK; i++) {
        CP_WAIT1();
        __syncthreads();
        if (i + 2 < NCHUNK)
            issue_chunk<MODE>(sbase, (i + 2) % NSTG, i + 2, m0, n0, tid);
        CP_COMMIT();
        compute_stage(sbase, i % NSTG, wm, wn, aLane, bLane, acc);
        __syncthreads();
    }

    // ---- epilogue ----
    int g = lane >> 2, t = lane & 3;
    if (MODE == 1) {
#pragma unroll
        for (int mt = 0; mt < 4; mt++) {
            int r0 = m0 + wm * 64 + mt * 16 + g;
#pragma unroll
            for (int nt = 0; nt < 4; nt++) {
                int cc = n0 + wn + nt * 8 + t * 2;
                float2 bv = *(const float2*)(bb + cc);
                float2 v0 = make_float2(acc[mt][nt][0] + bv.x, acc[mt][nt][1] + bv.y);
                float2 v1 = make_float2(acc[mt][nt][2] + bv.x, acc[mt][nt][3] + bv.y);
                *(float2*)(out + (size_t)r0 * ODIM + cc) = v0;
                *(float2*)(out + (size_t)(r0 + 8) * ODIM + cc) = v1;
            }
        }
    } else {
#pragma unroll
        for (int mt = 0; mt < 4; mt++) {
            int r0 = m0 + wm * 64 + mt * 16 + g;
            int r1 = r0 + 8;
#pragma unroll
            for (int nt = 0; nt < 4; nt++) {
                int cc = wn + nt * 8 + t * 2;
                int e = (wn + nt * 8) >> 4;
                float w0 = g_w[r0 * NEXP + e];
                float w1 = g_w[r1 * NEXP + e];
                float v00 = acc[mt][nt][0] * w0, v01 = acc[mt][nt][1] * w0;
                float v10 = acc[mt][nt][2] * w1, v11 = acc[mt][nt][3] * w1;
                __nv_bfloat16 h0, l0, h1, l1;
                split1(v00, h0, l0); split1(v01, h1, l1);
                ((__nv_bfloat162*)(g_ghi + (size_t)r0 * KLORA + cc))[0] = __nv_bfloat162(h0, h1);
                ((__nv_bfloat162*)(g_glo + (size_t)r0 * KLORA + cc))[0] = __nv_bfloat162(l0, l1);
                split1(v10, h0, l0); split1(v11, h1, l1);
                ((__nv_bfloat162*)(g_ghi + (size_t)r1 * KLORA + cc))[0] = __nv_bfloat162(h0, h1);
                ((__nv_bfloat162*)(g_glo + (size_t)r1 * KLORA + cc))[0] = __nv_bfloat162(l0, l1);
            }
        }
    }
}

// ---------------------------------------------------------------------------
extern "C" void kernel_launch(void* const* d_in, const int* in_sizes, int n_in,
                              void* d_out, int out_size) {
    const float* x  = (const float*)d_in[0];
    const float* Wb = (const float*)d_in[1];
    const float* bb = (const float*)d_in[2];
    const float* Wg = (const float*)d_in[3];
    const float* Wt = (const float*)d_in[4];
    const float* bt = (const float*)d_in[5];
    const float* Aw = (const float*)d_in[6];
    const float* Bw = (const float*)d_in[7];
    float* out = (float*)d_out;

    constexpr int SMEM_GEMM = NSTG * STAGE_B;   // 122880
    cudaFuncSetAttribute(hmma_gemm_kernel<0>, cudaFuncAttributeMaxDynamicSharedMemorySize, SMEM_GEMM);
    cudaFuncSetAttribute(hmma_gemm_kernel<1>, cudaFuncAttributeMaxDynamicSharedMemorySize, SMEM_GEMM);

    { int n4 = NTOK * DIM / 4;  split_kernel<<<(n4 + 255) / 256, 256>>>(x, 0, n4); }
    { int n4 = ODIM * DIM / 4;  split_kernel<<<(n4 + 255) / 256, 256>>>(Wb, 1, n4); }
    { int n4 = KLORA * DIM / 4; split_kernel<<<(n4 + 255) / 256, 256>>>(Aw, 2, n4); }
    build_bc_kernel<<<(ODIM * KLORA + 255) / 256, 256>>>(Bw);
    gate_kernel<<<NTOK / GT, 256>>>(x, Wg, Wt, bt);

    hmma_gemm_kernel<0><<<NTOK / 128, 256, SMEM_GEMM>>>(nullptr, nullptr);
    hmma_gemm_kernel<1><<<(NTOK / 128) * (ODIM / 128), 256, SMEM_GEMM>>>(bb, out);
}